// round 15
// baseline (speedup 1.0000x reference)
#include <cuda_runtime.h>
#include <math.h>

#define BC     4
#define NODES  4096
#define FEAT   64
#define OUTD   32
#define NEDGES (32 * NODES)
#define NW     (NODES / 32)   // 128 bitmap words per row
#define CAPW   128            // neighbor capacity (deg ~ Poisson(32))

// Scratch (no allocations in kernel_launch). g_bits is zero at module load;
// k_gat re-zeroes every word it consumes, so the bitmap is always clear when
// k_z_set's atomicOr scatter runs on the next call/replay.
__device__ float    g_z[BC * NODES * OUTD];   // 2 MB: z = h @ W
__device__ unsigned g_bits[NODES * NW];       // 2 MB: dedup'd adjacency bitmap

// ---------------------------------------------------------------------------
// Fused: z = h @ W (4 rows/warp -> 4 independent FMA chains; h warp-uniform
// float4, W staged in smem once per block) + edge scatter (1 edge/thread).
__global__ __launch_bounds__(128) void k_z_set(const float* __restrict__ h,
                                               const float* __restrict__ W,
                                               const int* __restrict__ erow,
                                               const int* __restrict__ ecol) {
    __shared__ __align__(16) float Ws[FEAT * OUTD];       // 8 KB
    const int tid = threadIdx.x;
#pragma unroll
    for (int i = 0; i < 4; i++)                            // 128*4 f4 = 8 KB
        ((float4*)Ws)[tid + 128 * i] = ((const float4*)W)[tid + 128 * i];

    const int gid = blockIdx.x * 128 + tid;                // exactly NEDGES
    {
        const int r = erow[gid], c = ecol[gid];
        atomicOr(&g_bits[r * NW + (c >> 5)], 1u << (c & 31));
    }
    __syncthreads();

    const int lane = tid & 31, wid = tid >> 5;
    const int r0 = (blockIdx.x * 4 + wid) * 4;             // 4 consecutive rows
    const float4* h4 = (const float4*)(h + (long)r0 * FEAT);
    float a0 = 0.f, a1 = 0.f, a2 = 0.f, a3 = 0.f;
#pragma unroll
    for (int q = 0; q < 16; q++) {
        const float4 h0 = h4[q];
        const float4 h1 = h4[16 + q];
        const float4 h2 = h4[32 + q];
        const float4 h3 = h4[48 + q];
        const float w0 = Ws[(4 * q + 0) * OUTD + lane];
        const float w1 = Ws[(4 * q + 1) * OUTD + lane];
        const float w2 = Ws[(4 * q + 2) * OUTD + lane];
        const float w3 = Ws[(4 * q + 3) * OUTD + lane];
        a0 = fmaf(h0.x, w0, a0); a0 = fmaf(h0.y, w1, a0);
        a0 = fmaf(h0.z, w2, a0); a0 = fmaf(h0.w, w3, a0);
        a1 = fmaf(h1.x, w0, a1); a1 = fmaf(h1.y, w1, a1);
        a1 = fmaf(h1.z, w2, a1); a1 = fmaf(h1.w, w3, a1);
        a2 = fmaf(h2.x, w0, a2); a2 = fmaf(h2.y, w1, a2);
        a2 = fmaf(h2.z, w2, a2); a2 = fmaf(h2.w, w3, a2);
        a3 = fmaf(h3.x, w0, a3); a3 = fmaf(h3.y, w1, a3);
        a3 = fmaf(h3.z, w2, a3); a3 = fmaf(h3.w, w3, a3);
    }
    g_z[(r0 + 0) * OUTD + lane] = a0;
    g_z[(r0 + 1) * OUTD + lane] = a1;
    g_z[(r0 + 2) * OUTD + lane] = a2;
    g_z[(r0 + 3) * OUTD + lane] = a3;
}

// ---------------------------------------------------------------------------
// Order-preserving float<->uint transform for __reduce_max_sync.
__device__ __forceinline__ unsigned f2ord(float f) {
    unsigned u = __float_as_uint(f);
    return (u & 0x80000000u) ? ~u : (u | 0x80000000u);
}
__device__ __forceinline__ float ord2f(unsigned u) {
    return __uint_as_float((u & 0x80000000u) ? (u & 0x7fffffffu) : ~u);
}

// One block per destination row; warp w owns batch w end-to-end.
// Phase A is built ONCE per block by warp 0 (warps 1-3 skip it; warp 1 zeroes
// the bitmap row concurrently). 16-row tiles; software-pipelined gather.
#define TROWS 16
#define TPAD  36
__global__ __launch_bounds__(128, 9) void k_gat(float* __restrict__ out) {
    __shared__ unsigned short nbr[CAPW];       // ONE shared list per block
    __shared__ int s_M;
    __shared__ __align__(16) float tile[4][TROWS * TPAD];
    __shared__ __align__(16) float s_zi[4][32];
    __shared__ __align__(16) float s_e[4][TROWS];

    const int row  = blockIdx.x;
    const int tid  = threadIdx.x;
    const int lane = tid & 31, wid = tid >> 5;

    const float*  zb  = g_z + wid * NODES * OUTD;
    const float4* zb4 = (const float4*)zb;

    // prefetch z_i (all warps, own batch)
    s_zi[wid][lane] = zb[row * OUTD + lane];

    // --- Phase A: warp 0 builds the list; warp 1 zeroes the bitmap ---
    int cnt = 0;
    uint4 wv;
    if (wid == 0) {
        wv = ((const uint4*)(g_bits + row * NW))[lane];
        cnt = __popc(wv.x) + __popc(wv.y) + __popc(wv.z) + __popc(wv.w);
        // cnt consumes wv -> the LDG is complete before the barrier below
    }
    __syncthreads();                           // order: read before zeroing
    if (wid == 1)                              // leave bitmap clean for next run
        ((uint4*)(g_bits + row * NW))[lane] = make_uint4(0u, 0u, 0u, 0u);
    if (wid == 0) {
        int v = cnt;
#pragma unroll
        for (int o = 1; o < 32; o <<= 1) {
            int t = __shfl_up_sync(0xffffffffu, v, o);
            if (lane >= o) v += t;
        }
        const int Mf = __shfl_sync(0xffffffffu, v, 31);
        int off = v - cnt;
        const int cb = lane * 128;
        unsigned ws[4] = {wv.x, wv.y, wv.z, wv.w};
#pragma unroll
        for (int q = 0; q < 4; q++) {
            unsigned ww = ws[q];
            while (ww) {
                int b = __ffs(ww) - 1;
                if (off < CAPW) nbr[off] = (unsigned short)(cb + q * 32 + b);
                off++;
                ww &= ww - 1;
            }
        }
        if (lane == 0) s_M = (Mf > CAPW) ? CAPW : Mf;
    }
    __syncthreads();                           // publish nbr + s_M
    const int M = s_M;

    // --- Phase B: warp `wid` = batch `wid` (software-pipelined gather) ---
    float*  tw  = tile[wid];
    float4* tw4 = (float4*)tw;
    const float* twl = tw + lane;              // immediate-offset base
    const float4* se4 = (const float4*)s_e[wid];
    const int kn   = lane >> 1;                // neighbor slot 0..15
    const int half = lane & 1;                 // which 16 features of the dot
    const int krow = lane >> 3;                // staging row group 0..3
    const int d4   = lane & 7;                 // staging f4 index 0..7

    float m = -INFINITY, ssum = 0.f;
    float acc0 = 0.f, acc1 = 0.f;

    // prologue: prefetch tile 0 into registers (clamped tail rows)
    float4 pre0, pre1, pre2, pre3;
    {
        const bool inr0 = (kn < ((M < TROWS) ? M : TROWS));
        const int  j0   = nbr[inr0 ? kn : 0];
        pre0 = zb4[__shfl_sync(0xffffffffu, j0, 2 * (krow +  0)) * 8 + d4];
        pre1 = zb4[__shfl_sync(0xffffffffu, j0, 2 * (krow +  4)) * 8 + d4];
        pre2 = zb4[__shfl_sync(0xffffffffu, j0, 2 * (krow +  8)) * 8 + d4];
        pre3 = zb4[__shfl_sync(0xffffffffu, j0, 2 * (krow + 12)) * 8 + d4];
    }

    for (int t = 0; t < M; t += TROWS) {
        const bool inr = (t + kn < M);

        // store the prefetched tile
        tw4[(krow +  0) * 9 + d4] = pre0;
        tw4[(krow +  4) * 9 + d4] = pre1;
        tw4[(krow +  8) * 9 + d4] = pre2;
        tw4[(krow + 12) * 9 + d4] = pre3;
        __syncwarp();

        // issue next tile's gathers NOW (latency overlaps compute below)
        if (t + TROWS < M) {
            const bool inr2 = (t + TROWS + kn < M);
            const int  j2   = nbr[t + TROWS + (inr2 ? kn : 0)];
            pre0 = zb4[__shfl_sync(0xffffffffu, j2, 2 * (krow +  0)) * 8 + d4];
            pre1 = zb4[__shfl_sync(0xffffffffu, j2, 2 * (krow +  4)) * 8 + d4];
            pre2 = zb4[__shfl_sync(0xffffffffu, j2, 2 * (krow +  8)) * 8 + d4];
            pre3 = zb4[__shfl_sync(0xffffffffu, j2, 2 * (krow + 12)) * 8 + d4];
        }

        // half-dot: lane (2k+half) covers features [16*half, 16*half+16)
        float dd0 = 0.f, dd1 = 0.f;
#pragma unroll
        for (int i = 0; i < 4; i++) {
            const float4 vv = tw4[kn * 9 + half * 4 + i];
            const int f = half * 16 + 4 * i;
            dd0 = fmaf(vv.x, s_zi[wid][f + 0], dd0);
            dd1 = fmaf(vv.y, s_zi[wid][f + 1], dd1);
            dd0 = fmaf(vv.z, s_zi[wid][f + 2], dd0);
            dd1 = fmaf(vv.w, s_zi[wid][f + 3], dd1);
        }
        float p = dd0 + dd1;
        p += __shfl_xor_sync(0xffffffffu, p, 1);              // combine halves
        const float s = (p >= 0.f) ? p : 0.1f * p;            // LeakyReLU(0.1)
        const bool  valid = inr && (s != 0.f);                // att==0 -> masked
        const float sv = valid ? s : -INFINITY;

        const float tm = ord2f(__reduce_max_sync(0xffffffffu, f2ord(sv)));
        const float nm = fmaxf(m, tm);

        if (nm > -INFINITY) {                                 // warp-uniform
            const float e = valid ? __expf(sv - nm) : 0.f;
            if (half == 0) s_e[wid][kn] = e;                  // e=0 on tail rows
            if (m > -INFINITY) {                              // skip first tile
                const float corr = __expf(m - nm);
                acc0 *= corr;  acc1 *= corr;  ssum *= corr;
            }
            __syncwarp();
            // fully unrolled aggregation: immediate smem offsets, no tail
            const float4 e0 = se4[0], e1 = se4[1];
            const float4 e2 = se4[2], e3 = se4[3];
            acc0 = fmaf(e0.x, twl[ 0 * TPAD], acc0);
            acc1 = fmaf(e0.y, twl[ 1 * TPAD], acc1);
            acc0 = fmaf(e0.z, twl[ 2 * TPAD], acc0);
            acc1 = fmaf(e0.w, twl[ 3 * TPAD], acc1);
            acc0 = fmaf(e1.x, twl[ 4 * TPAD], acc0);
            acc1 = fmaf(e1.y, twl[ 5 * TPAD], acc1);
            acc0 = fmaf(e1.z, twl[ 6 * TPAD], acc0);
            acc1 = fmaf(e1.w, twl[ 7 * TPAD], acc1);
            acc0 = fmaf(e2.x, twl[ 8 * TPAD], acc0);
            acc1 = fmaf(e2.y, twl[ 9 * TPAD], acc1);
            acc0 = fmaf(e2.z, twl[10 * TPAD], acc0);
            acc1 = fmaf(e2.w, twl[11 * TPAD], acc1);
            acc0 = fmaf(e3.x, twl[12 * TPAD], acc0);
            acc1 = fmaf(e3.y, twl[13 * TPAD], acc1);
            acc0 = fmaf(e3.z, twl[14 * TPAD], acc0);
            acc1 = fmaf(e3.w, twl[15 * TPAD], acc1);
            const float t0 = (e0.x + e0.y) + (e0.z + e0.w);
            const float t1 = (e1.x + e1.y) + (e1.z + e1.w);
            const float t2 = (e2.x + e2.y) + (e2.z + e2.w);
            const float t3 = (e3.x + e3.y) + (e3.z + e3.w);
            ssum += (t0 + t1) + (t2 + t3);
            m = nm;
        }
        __syncwarp();
    }

    float o;
    if (m > -INFINITY) {
        o = (acc0 + acc1) / ssum;
    } else {
        // fully-masked row: softmax uniform over ALL 4096 columns
        float s2 = 0.f;
        for (int n = 0; n < NODES; n++) s2 += zb[n * OUTD + lane];
        o = s2 * (1.f / (float)NODES);
    }
    out[(wid * NODES + row) * OUTD + lane] = o;
}

// ---------------------------------------------------------------------------
extern "C" void kernel_launch(void* const* d_in, const int* in_sizes, int n_in,
                              void* d_out, int out_size) {
    const float* h       = (const float*)d_in[0];
    const float* W       = (const float*)d_in[1];
    const int*   adj_row = (const int*)d_in[2];
    const int*   adj_col = (const int*)d_in[3];
    float*       out     = (float*)d_out;

    k_z_set<<<NEDGES / 128, 128>>>(h, W, adj_row, adj_col);
    k_gat  <<<NODES, 128>>>(out);
}

// round 17
// speedup vs baseline: 1.0809x; 1.0809x over previous
#include <cuda_runtime.h>
#include <math.h>

#define BC     4
#define NODES  4096
#define FEAT   64
#define OUTD   32
#define NEDGES (32 * NODES)
#define NW     (NODES / 32)   // 128 bitmap words per row
#define CAPW   128            // neighbor capacity (deg ~ Poisson(32))
#define CAPS   (CAPW + 8)     // padded for uint4 group loads

// Scratch (no allocations in kernel_launch). g_bits is zero at module load;
// k_gat re-zeroes every word it consumes, so the bitmap is always clear when
// k_z_set's atomicOr scatter runs on the next call/replay.
__device__ float    g_z[BC * NODES * OUTD];   // 2 MB: z = h @ W
__device__ unsigned g_bits[NODES * NW];       // 2 MB: dedup'd adjacency bitmap

// ---------------------------------------------------------------------------
// Fused: z = h @ W (4 rows/warp -> 4 independent FMA chains; h warp-uniform
// float4, W staged in smem once per block) + edge scatter (1 edge/thread).
__global__ __launch_bounds__(128) void k_z_set(const float* __restrict__ h,
                                               const float* __restrict__ W,
                                               const int* __restrict__ erow,
                                               const int* __restrict__ ecol) {
    __shared__ __align__(16) float Ws[FEAT * OUTD];       // 8 KB
    const int tid = threadIdx.x;
#pragma unroll
    for (int i = 0; i < 4; i++)                            // 128*4 f4 = 8 KB
        ((float4*)Ws)[tid + 128 * i] = ((const float4*)W)[tid + 128 * i];

    const int gid = blockIdx.x * 128 + tid;                // exactly NEDGES
    {
        const int r = erow[gid], c = ecol[gid];
        atomicOr(&g_bits[r * NW + (c >> 5)], 1u << (c & 31));
    }
    __syncthreads();

    const int lane = tid & 31, wid = tid >> 5;
    const int r0 = (blockIdx.x * 4 + wid) * 4;             // 4 consecutive rows
    const float4* h4 = (const float4*)(h + (long)r0 * FEAT);
    float a0 = 0.f, a1 = 0.f, a2 = 0.f, a3 = 0.f;
#pragma unroll
    for (int q = 0; q < 16; q++) {
        const float4 h0 = h4[q];
        const float4 h1 = h4[16 + q];
        const float4 h2 = h4[32 + q];
        const float4 h3 = h4[48 + q];
        const float w0 = Ws[(4 * q + 0) * OUTD + lane];
        const float w1 = Ws[(4 * q + 1) * OUTD + lane];
        const float w2 = Ws[(4 * q + 2) * OUTD + lane];
        const float w3 = Ws[(4 * q + 3) * OUTD + lane];
        a0 = fmaf(h0.x, w0, a0); a0 = fmaf(h0.y, w1, a0);
        a0 = fmaf(h0.z, w2, a0); a0 = fmaf(h0.w, w3, a0);
        a1 = fmaf(h1.x, w0, a1); a1 = fmaf(h1.y, w1, a1);
        a1 = fmaf(h1.z, w2, a1); a1 = fmaf(h1.w, w3, a1);
        a2 = fmaf(h2.x, w0, a2); a2 = fmaf(h2.y, w1, a2);
        a2 = fmaf(h2.z, w2, a2); a2 = fmaf(h2.w, w3, a2);
        a3 = fmaf(h3.x, w0, a3); a3 = fmaf(h3.y, w1, a3);
        a3 = fmaf(h3.z, w2, a3); a3 = fmaf(h3.w, w3, a3);
    }
    g_z[(r0 + 0) * OUTD + lane] = a0;
    g_z[(r0 + 1) * OUTD + lane] = a1;
    g_z[(r0 + 2) * OUTD + lane] = a2;
    g_z[(r0 + 3) * OUTD + lane] = a3;
}

// ---------------------------------------------------------------------------
// One block per destination row; warp w owns batch w end-to-end.
// Lane layout: quarter q8 = lane>>3 owns one neighbor; f8 = lane&7 indexes a
// float4 of features. Per 4 neighbors: 1 LDG.128, dot = 4 FMA + 3 shfl (the
// sum lands in the owning group -> e needs NO broadcast), max = 2 shfl.
// Aggregation is register-resident float4 FMAs; cross-group fold once at end.
__global__ __launch_bounds__(128, 10) void k_gat(float* __restrict__ out) {
    __shared__ __align__(16) unsigned short nbr[CAPS];    // one list per block
    __shared__ int s_M;

    const int row  = blockIdx.x;
    const int tid  = threadIdx.x;
    const int lane = tid & 31, wid = tid >> 5;
    const int q8   = lane >> 3;               // neighbor slot within group of 4
    const int f8   = lane & 7;                // float4 chunk of the z row

    const float*  zb  = g_z + wid * NODES * OUTD;
    const float4* zb4 = (const float4*)zb;    // 8 float4 per node row

    // prefetch z_i chunk (all warps, own batch)
    const float4 zi4 = zb4[row * 8 + f8];

    // --- Phase A: warp 0 builds the shared list; warp 1 zeroes the bitmap ---
    int cnt = 0;
    uint4 wv;
    if (wid == 0) {
        wv = ((const uint4*)(g_bits + row * NW))[lane];
        cnt = __popc(wv.x) + __popc(wv.y) + __popc(wv.z) + __popc(wv.w);
        // cnt consumes wv -> the LDG completed before the barrier below
    }
    __syncthreads();                           // order: read before zeroing
    if (wid == 1)                              // leave bitmap clean for next run
        ((uint4*)(g_bits + row * NW))[lane] = make_uint4(0u, 0u, 0u, 0u);
    if (wid == 0) {
        int v = cnt;
#pragma unroll
        for (int o = 1; o < 32; o <<= 1) {
            int t = __shfl_up_sync(0xffffffffu, v, o);
            if (lane >= o) v += t;
        }
        int Mf = __shfl_sync(0xffffffffu, v, 31);
        int off = v - cnt;
        const int cb = lane * 128;
        unsigned ws[4] = {wv.x, wv.y, wv.z, wv.w};
#pragma unroll
        for (int q = 0; q < 4; q++) {
            unsigned ww = ws[q];
            while (ww) {
                int b = __ffs(ww) - 1;
                if (off < CAPW) nbr[off] = (unsigned short)(cb + q * 32 + b);
                off++;
                ww &= ww - 1;
            }
        }
        if (Mf > CAPW) Mf = CAPW;
        __syncwarp();                          // nbr[0] visible to all lanes
        if (lane < 8 && Mf > 0)                // pad with a VALID index
            nbr[Mf + lane] = nbr[0];
        if (lane == 0) s_M = Mf;
    }
    __syncthreads();                           // publish nbr + s_M
    const int M = s_M;

    // --- Phase B: online softmax + register-resident aggregation ---
    float  m = -INFINITY, ssum = 0.f;
    float4 acc = make_float4(0.f, 0.f, 0.f, 0.f);

    for (int t = 0; t < M; t += 8) {
        // 8 neighbor ids in one LDS.128 broadcast (padding keeps it valid)
        const uint4 nv = *(const uint4*)(&nbr[t]);
        const unsigned w0 = (q8 & 2) ? nv.y : nv.x;
        const unsigned w1 = (q8 & 2) ? nv.w : nv.z;
        const int j0 = (q8 & 1) ? (int)(w0 >> 16) : (int)(w0 & 0xffffu);
        const int j1 = (q8 & 1) ? (int)(w1 >> 16) : (int)(w1 & 0xffffu);

        // two independent 4-neighbor gathers (each: 4 rows via LDG.128)
        const float4 za = zb4[j0 * 8 + f8];
        const float4 zc = zb4[j1 * 8 + f8];

        // partial dots (4 FMA each), then 3-step butterfly within 8-lane group
        float d0 = za.x * zi4.x;  d0 = fmaf(za.y, zi4.y, d0);
        d0 = fmaf(za.z, zi4.z, d0);  d0 = fmaf(za.w, zi4.w, d0);
        float d1 = zc.x * zi4.x;  d1 = fmaf(zc.y, zi4.y, d1);
        d1 = fmaf(zc.z, zi4.z, d1);  d1 = fmaf(zc.w, zi4.w, d1);
        d0 += __shfl_xor_sync(0xffffffffu, d0, 4);
        d1 += __shfl_xor_sync(0xffffffffu, d1, 4);
        d0 += __shfl_xor_sync(0xffffffffu, d0, 2);
        d1 += __shfl_xor_sync(0xffffffffu, d1, 2);
        d0 += __shfl_xor_sync(0xffffffffu, d0, 1);
        d1 += __shfl_xor_sync(0xffffffffu, d1, 1);
        // d0/d1 now hold the OWN group's neighbor score (uniform in group)

        // LeakyReLU(0.1) + mask (att==0 or padded slot -> -inf)
        float s0 = (d0 >= 0.f) ? d0 : 0.1f * d0;
        float s1 = (d1 >= 0.f) ? d1 : 0.1f * d1;
        s0 = (t + q8     < M && s0 != 0.f) ? s0 : -INFINITY;
        s1 = (t + 4 + q8 < M && s1 != 0.f) ? s1 : -INFINITY;

        // warp max of all 8 scores: 2 shfl per chain
        float g = fmaxf(s0, s1);
        g = fmaxf(g, __shfl_xor_sync(0xffffffffu, g, 8));
        g = fmaxf(g, __shfl_xor_sync(0xffffffffu, g, 16));
        const float nm = fmaxf(m, g);

        if (nm > -INFINITY) {                  // warp-uniform branch
            const float corr = __expf(m - nm); // 0 when m == -inf
            const float e0 = __expf(s0 - nm);  // 0 for masked/padded
            const float e1 = __expf(s1 - nm);
            acc.x = fmaf(acc.x, corr, fmaf(e0, za.x, e1 * zc.x));
            acc.y = fmaf(acc.y, corr, fmaf(e0, za.y, e1 * zc.y));
            acc.z = fmaf(acc.z, corr, fmaf(e0, za.z, e1 * zc.z));
            acc.w = fmaf(acc.w, corr, fmaf(e0, za.w, e1 * zc.w));
            ssum  = fmaf(ssum, corr, e0 + e1); // own-group e's only
            m = nm;
        }
    }

    // fold partial sums across the 4 groups (once)
    acc.x += __shfl_xor_sync(0xffffffffu, acc.x, 8);
    acc.y += __shfl_xor_sync(0xffffffffu, acc.y, 8);
    acc.z += __shfl_xor_sync(0xffffffffu, acc.z, 8);
    acc.w += __shfl_xor_sync(0xffffffffu, acc.w, 8);
    ssum  += __shfl_xor_sync(0xffffffffu, ssum,  8);
    acc.x += __shfl_xor_sync(0xffffffffu, acc.x, 16);
    acc.y += __shfl_xor_sync(0xffffffffu, acc.y, 16);
    acc.z += __shfl_xor_sync(0xffffffffu, acc.z, 16);
    acc.w += __shfl_xor_sync(0xffffffffu, acc.w, 16);
    ssum  += __shfl_xor_sync(0xffffffffu, ssum,  16);

    float4 o4;
    if (m > -INFINITY) {
        const float inv = 1.0f / ssum;
        o4 = make_float4(acc.x * inv, acc.y * inv, acc.z * inv, acc.w * inv);
    } else {
        // fully-masked row: softmax uniform over ALL 4096 columns
        float4 s4 = make_float4(0.f, 0.f, 0.f, 0.f);
        for (int n = 0; n < NODES; n++) {
            const float4 zv = zb4[n * 8 + f8];
            s4.x += zv.x;  s4.y += zv.y;  s4.z += zv.z;  s4.w += zv.w;
        }
        const float inv = 1.0f / (float)NODES;
        o4 = make_float4(s4.x * inv, s4.y * inv, s4.z * inv, s4.w * inv);
    }
    if (lane < 8)
        ((float4*)(out + ((long)wid * NODES + row) * OUTD))[f8] = o4;
}

// ---------------------------------------------------------------------------
extern "C" void kernel_launch(void* const* d_in, const int* in_sizes, int n_in,
                              void* d_out, int out_size) {
    const float* h       = (const float*)d_in[0];
    const float* W       = (const float*)d_in[1];
    const int*   adj_row = (const int*)d_in[2];
    const int*   adj_col = (const int*)d_in[3];
    float*       out     = (float*)d_out;

    k_z_set<<<NEDGES / 128, 128>>>(h, W, adj_row, adj_col);
    k_gat  <<<NODES, 128>>>(out);
}